// round 1
// baseline (speedup 1.0000x reference)
#include <cuda_runtime.h>

// ---------------- problem constants ----------------
#define BB    8
#define SS    2048
#define PLM   768
#define GG    256
#define NWM   50000
#define EWM   800000
#define NF    16384           // B*S
#define EF    131072
#define KSLOT 4
#define G4    (GG/4)          // 64 float4 per G-row
#define PLM4  (PLM/4)         // 192 float4 per PLM-row
#define CAT3  (PLM + 2*GG)    // 1280
#define CAT34 (CAT3/4)        // 320
#define CAT1  (GG + PLM)      // 1024
#define CAT14 (CAT1/4)        // 256

// ---------------- device scratch (no runtime alloc allowed) ----------------
__device__ __align__(16) float g_bufM[(size_t)NWM * GG];   // h+m accumulator (WM)
__device__ __align__(16) float g_bufH[(size_t)NWM * GG];   // layer output (WM)
__device__ __align__(16) float g_tmp [(size_t)NF * GG];    // per-token concept sum
__device__ __align__(16) float g_gte [(size_t)NF * GG];    // graph_text_embed
__device__ __align__(16) float g_fM  [(size_t)NF * GG];    // h+m accumulator (FSTM)
__device__ __align__(16) float g_fH  [(size_t)NF * GG];    // layer output (FSTM)
__device__ __align__(16) float g_cat [(size_t)NF * CAT3];  // concat buffer (1024 or 1280 cols)

__device__ int g_wm_rowptr[NWM + 1];
__device__ int g_wm_cur[NWM];
__device__ int g_wm_col[EWM];
__device__ int g_f_rowptr[NF + 1];
__device__ int g_f_cur[NF];
__device__ int g_f_col[EF];

// ---------------- small kernels ----------------
__global__ void zero_int_kernel(int* __restrict__ p, int n) {
    int i = blockIdx.x * blockDim.x + threadIdx.x;
    if (i < n) p[i] = 0;
}

__global__ void hist_kernel(const int* __restrict__ dst, int* __restrict__ cnt, int E) {
    int e = blockIdx.x * blockDim.x + threadIdx.x;
    if (e < E) atomicAdd(&cnt[dst[e]], 1);
}

// single block, 1024 threads. cnt_cur: in = counts, out = exclusive prefix (cursor copy)
__global__ void scan_kernel(int* __restrict__ cnt_cur, int* __restrict__ rowptr, int N, int E) {
    __shared__ int sh[1024];
    int tid = threadIdx.x;
    int chunk = (N + 1023) >> 10;
    int s0 = tid * chunk;
    int s1 = s0 + chunk; if (s1 > N) s1 = N;
    int s = 0;
    for (int i = s0; i < s1; i++) s += cnt_cur[i];
    sh[tid] = s;
    __syncthreads();
    for (int off = 1; off < 1024; off <<= 1) {
        int v = (tid >= off) ? sh[tid - off] : 0;
        __syncthreads();
        sh[tid] += v;
        __syncthreads();
    }
    int run = sh[tid] - s;  // exclusive base for this thread
    for (int i = s0; i < s1; i++) {
        int c = cnt_cur[i];
        rowptr[i]  = run;
        cnt_cur[i] = run;   // cursor for fill phase
        run += c;
    }
    if (tid == 0) rowptr[N] = E;
}

__global__ void fill_kernel(const int* __restrict__ src, const int* __restrict__ dst,
                            int* __restrict__ cur, int* __restrict__ col, int E) {
    int e = blockIdx.x * blockDim.x + threadIdx.x;
    if (e < E) {
        int d = dst[e];
        int p = atomicAdd(&cur[d], 1);
        col[p] = src[e];
    }
}

// out[n] = h[n] + sum_{edges into n} h[src]
__global__ void spmm_self_kernel(const float4* __restrict__ h,
                                 const int* __restrict__ rowptr,
                                 const int* __restrict__ col,
                                 float4* __restrict__ out, int n) {
    int node = blockIdx.x * blockDim.y + threadIdx.y;
    if (node >= n) return;
    int x = threadIdx.x;  // 0..63
    float4 acc = h[(size_t)node * G4 + x];
    int e  = rowptr[node];
    int e1 = rowptr[node + 1];
    for (; e < e1; ++e) {
        int s = __ldg(&col[e]);
        float4 v = __ldg(&h[(size_t)s * G4 + x]);
        acc.x += v.x; acc.y += v.y; acc.z += v.z; acc.w += v.w;
    }
    out[(size_t)node * G4 + x] = acc;
}

// tmp[row] = sum_{k<4} ge[t2n[row*4+k]]
__global__ void gather4sum_kernel(const float4* __restrict__ ge,
                                  const int* __restrict__ t2n,
                                  float4* __restrict__ out, int rows) {
    int row = blockIdx.x * blockDim.y + threadIdx.y;
    if (row >= rows) return;
    int x = threadIdx.x;
    float4 acc = make_float4(0.f, 0.f, 0.f, 0.f);
#pragma unroll
    for (int k = 0; k < KSLOT; k++) {
        int idx = __ldg(&t2n[row * KSLOT + k]);
        float4 v = __ldg(&ge[(size_t)idx * G4 + x]);
        acc.x += v.x; acc.y += v.y; acc.z += v.z; acc.w += v.w;
    }
    out[(size_t)row * G4 + x] = acc;
}

__global__ void gather_rows_kernel(const float4* __restrict__ src,
                                   const int* __restrict__ ids,
                                   float4* __restrict__ out, int rows) {
    int row = blockIdx.x * blockDim.y + threadIdx.y;
    if (row >= rows) return;
    int id = ids[row];
    out[(size_t)row * G4 + threadIdx.x] = src[(size_t)id * G4 + threadIdx.x];
}

// cat1[row, :] = [tmp(256) | text(768)]  -> 256 float4 per row
__global__ void concat2_kernel(const float4* __restrict__ a,      // 64 f4/row
                               const float4* __restrict__ btxt,   // 192 f4/row
                               float4* __restrict__ out, int rows) {
    int idx = blockIdx.x * blockDim.x + threadIdx.x;
    if (idx >= rows * CAT14) return;
    int row = idx >> 8;         // /256
    int c   = idx & 255;
    out[idx] = (c < G4) ? a[(size_t)row * G4 + c]
                        : btxt[(size_t)row * PLM4 + (c - G4)];
}

// final[row, :] = [text(768) | tmp(256) | temporal(256)] -> 320 float4 per row
__global__ void concat3_kernel(const float4* __restrict__ txt,
                               const float4* __restrict__ tmpv,
                               const float4* __restrict__ tempo,
                               float4* __restrict__ out, int rows) {
    int idx = blockIdx.x * blockDim.x + threadIdx.x;
    if (idx >= rows * CAT34) return;
    int row = idx / CAT34;
    int c   = idx - row * CAT34;
    float4 v;
    if (c < PLM4)            v = txt[(size_t)row * PLM4 + c];
    else if (c < PLM4 + G4)  v = tmpv[(size_t)row * G4 + (c - PLM4)];
    else                     v = tempo[(size_t)row * G4 + (c - PLM4 - G4)];
    out[idx] = v;
}

// ---------------- SGEMM: C = A(MxK) * B(KxN) + bias, optional relu ----------------
// 128x128 block tile, BK=8, 256 threads, 8x8 per thread (split 4+4 fragments).
// Requires: N % 128 == 0, K % 8 == 0 (true for all call sites). M arbitrary.
__global__ __launch_bounds__(256)
void sgemm_kernel(const float* __restrict__ A, const float* __restrict__ Bm,
                  const float* __restrict__ bias, float* __restrict__ C,
                  int M, int N, int K, int dorelu) {
    __shared__ float As[2][8][128];
    __shared__ float Bs[2][8][128];

    const int tid = threadIdx.x;
    const int bm = blockIdx.y * 128;
    const int bn = blockIdx.x * 128;
    const int tx = tid & 15;
    const int ty = tid >> 4;

    const int a_row = tid >> 1;         // 0..127
    const int a_k   = (tid & 1) * 4;    // 0 or 4
    const int b_k   = tid >> 5;         // 0..7
    const int b_n   = (tid & 31) * 4;   // 0..124

    const bool arow_ok = (bm + a_row) < M;
    const float* Aptr = A + (size_t)(bm + a_row) * K + a_k;
    const float* Bptr = Bm + (size_t)b_k * N + bn + b_n;

    float4 pa = arow_ok ? *(const float4*)Aptr : make_float4(0.f, 0.f, 0.f, 0.f);
    float4 pb = *(const float4*)Bptr;

    As[0][a_k + 0][a_row] = pa.x;
    As[0][a_k + 1][a_row] = pa.y;
    As[0][a_k + 2][a_row] = pa.z;
    As[0][a_k + 3][a_row] = pa.w;
    *(float4*)&Bs[0][b_k][b_n] = pb;
    __syncthreads();

    float acc[8][8];
#pragma unroll
    for (int i = 0; i < 8; i++)
#pragma unroll
        for (int j = 0; j < 8; j++) acc[i][j] = 0.f;

    const int nk = K >> 3;
    int cur = 0;
    for (int t = 0; t < nk; ++t) {
        if (t + 1 < nk) {
            int kk = (t + 1) << 3;
            pa = arow_ok ? *(const float4*)(Aptr + kk) : make_float4(0.f, 0.f, 0.f, 0.f);
            pb = *(const float4*)(Bptr + (size_t)kk * N);
        }
#pragma unroll
        for (int k = 0; k < 8; ++k) {
            float4 a0 = *(const float4*)&As[cur][k][ty * 4];
            float4 a1 = *(const float4*)&As[cur][k][64 + ty * 4];
            float4 b0 = *(const float4*)&Bs[cur][k][tx * 4];
            float4 b1 = *(const float4*)&Bs[cur][k][64 + tx * 4];
            float af[8] = {a0.x, a0.y, a0.z, a0.w, a1.x, a1.y, a1.z, a1.w};
            float bf[8] = {b0.x, b0.y, b0.z, b0.w, b1.x, b1.y, b1.z, b1.w};
#pragma unroll
            for (int i = 0; i < 8; i++)
#pragma unroll
                for (int j = 0; j < 8; j++) acc[i][j] += af[i] * bf[j];
        }
        if (t + 1 < nk) {
            int nxt = cur ^ 1;
            As[nxt][a_k + 0][a_row] = pa.x;
            As[nxt][a_k + 1][a_row] = pa.y;
            As[nxt][a_k + 2][a_row] = pa.z;
            As[nxt][a_k + 3][a_row] = pa.w;
            *(float4*)&Bs[nxt][b_k][b_n] = pb;
            __syncthreads();
            cur = nxt;
        }
    }

    float4 bv0 = *(const float4*)&bias[bn + tx * 4];
    float4 bv1 = *(const float4*)&bias[bn + 64 + tx * 4];

#pragma unroll
    for (int hi = 0; hi < 2; hi++) {
#pragma unroll
        for (int i = 0; i < 4; i++) {
            int row = bm + hi * 64 + ty * 4 + i;
            if (row < M) {
                int ii = hi * 4 + i;
                float4 o0 = make_float4(acc[ii][0] + bv0.x, acc[ii][1] + bv0.y,
                                        acc[ii][2] + bv0.z, acc[ii][3] + bv0.w);
                float4 o1 = make_float4(acc[ii][4] + bv1.x, acc[ii][5] + bv1.y,
                                        acc[ii][6] + bv1.z, acc[ii][7] + bv1.w);
                if (dorelu) {
                    o0.x = fmaxf(o0.x, 0.f); o0.y = fmaxf(o0.y, 0.f);
                    o0.z = fmaxf(o0.z, 0.f); o0.w = fmaxf(o0.w, 0.f);
                    o1.x = fmaxf(o1.x, 0.f); o1.y = fmaxf(o1.y, 0.f);
                    o1.z = fmaxf(o1.z, 0.f); o1.w = fmaxf(o1.w, 0.f);
                }
                *(float4*)&C[(size_t)row * N + bn + tx * 4]      = o0;
                *(float4*)&C[(size_t)row * N + bn + 64 + tx * 4] = o1;
            }
        }
    }
}

// ---------------- host launcher ----------------
extern "C" void kernel_launch(void* const* d_in, const int* in_sizes, int n_in,
                              void* d_out, int out_size) {
    (void)in_sizes; (void)n_in; (void)out_size;

    const float* text   = (const float*)d_in[0];   // [B,S,PLM] -> [NF, PLM]
    const float* wm_x   = (const float*)d_in[1];   // [NWM, G]
    const int*   wm_ei  = (const int*)  d_in[2];   // [2, EWM]
    const int*   t2n    = (const int*)  d_in[3];   // [NF, 4]
    const int*   fids   = (const int*)  d_in[4];   // [NF]
    const int*   f_ei   = (const int*)  d_in[5];   // [2, EF]
    // d_in[6] extra_emb: unreachable (indices always >= 2)
    const float* wm_W1  = (const float*)d_in[7];
    const float* wm_b1  = (const float*)d_in[8];
    const float* wm_W2  = (const float*)d_in[9];
    const float* wm_b2  = (const float*)d_in[10];
    const float* f_W1   = (const float*)d_in[11];
    const float* f_b1   = (const float*)d_in[12];
    const float* f_W2   = (const float*)d_in[13];
    const float* f_b2   = (const float*)d_in[14];
    const float* fc1_W  = (const float*)d_in[15];
    const float* fc1_b  = (const float*)d_in[16];
    const float* fc3_W  = (const float*)d_in[17];
    const float* fc3_b  = (const float*)d_in[18];
    float* out = (float*)d_out;

    float *bufM, *bufH, *tmpb, *gte, *fM, *fH, *cat;
    int *wrp, *wcur, *wcol, *frp, *fcur, *fcol;
    cudaGetSymbolAddress((void**)&bufM, g_bufM);
    cudaGetSymbolAddress((void**)&bufH, g_bufH);
    cudaGetSymbolAddress((void**)&tmpb, g_tmp);
    cudaGetSymbolAddress((void**)&gte,  g_gte);
    cudaGetSymbolAddress((void**)&fM,   g_fM);
    cudaGetSymbolAddress((void**)&fH,   g_fH);
    cudaGetSymbolAddress((void**)&cat,  g_cat);
    cudaGetSymbolAddress((void**)&wrp,  g_wm_rowptr);
    cudaGetSymbolAddress((void**)&wcur, g_wm_cur);
    cudaGetSymbolAddress((void**)&wcol, g_wm_col);
    cudaGetSymbolAddress((void**)&frp,  g_f_rowptr);
    cudaGetSymbolAddress((void**)&fcur, g_f_cur);
    cudaGetSymbolAddress((void**)&fcol, g_f_col);

    const dim3 bSp(64, 4);

    // ===== WM CSR build (rows = dst, cols = src) =====
    zero_int_kernel<<<(NWM + 255) / 256, 256>>>(wcur, NWM);
    hist_kernel<<<(EWM + 255) / 256, 256>>>(wm_ei + EWM, wcur, EWM);
    scan_kernel<<<1, 1024>>>(wcur, wrp, NWM, EWM);
    fill_kernel<<<(EWM + 255) / 256, 256>>>(wm_ei, wm_ei + EWM, wcur, wcol, EWM);

    // ===== WM GNN: 2 layers =====
    spmm_self_kernel<<<(NWM + 3) / 4, bSp>>>((const float4*)wm_x, wrp, wcol, (float4*)bufM, NWM);
    sgemm_kernel<<<dim3(GG / 128, (NWM + 127) / 128), 256>>>(bufM, wm_W1, wm_b1, bufH, NWM, GG, GG, 1);
    spmm_self_kernel<<<(NWM + 3) / 4, bSp>>>((const float4*)bufH, wrp, wcol, (float4*)bufM, NWM);
    sgemm_kernel<<<dim3(GG / 128, (NWM + 127) / 128), 256>>>(bufM, wm_W2, wm_b2, bufH, NWM, GG, GG, 1);
    // bufH = graph_embeddings [NWM, G]

    // ===== token concept sum + fc1 =====
    gather4sum_kernel<<<(NF + 3) / 4, bSp>>>((const float4*)bufH, t2n, (float4*)tmpb, NF);
    concat2_kernel<<<(NF * CAT14 + 255) / 256, 256>>>((const float4*)tmpb, (const float4*)text,
                                                      (float4*)cat, NF);
    sgemm_kernel<<<dim3(GG / 128, NF / 128), 256>>>(cat, fc1_W, fc1_b, gte, NF, GG, CAT1, 0);

    // ===== FSTM: gather + CSR + 2 layers =====
    gather_rows_kernel<<<(NF + 3) / 4, bSp>>>((const float4*)gte, fids, (float4*)fH, NF);

    zero_int_kernel<<<(NF + 255) / 256, 256>>>(fcur, NF);
    hist_kernel<<<(EF + 255) / 256, 256>>>(f_ei + EF, fcur, EF);
    scan_kernel<<<1, 1024>>>(fcur, frp, NF, EF);
    fill_kernel<<<(EF + 255) / 256, 256>>>(f_ei, f_ei + EF, fcur, fcol, EF);

    spmm_self_kernel<<<(NF + 3) / 4, bSp>>>((const float4*)fH, frp, fcol, (float4*)fM, NF);
    sgemm_kernel<<<dim3(GG / 128, NF / 128), 256>>>(fM, f_W1, f_b1, fH, NF, GG, GG, 1);
    spmm_self_kernel<<<(NF + 3) / 4, bSp>>>((const float4*)fH, frp, fcol, (float4*)fM, NF);
    sgemm_kernel<<<dim3(GG / 128, NF / 128), 256>>>(fM, f_W2, f_b2, fH, NF, GG, GG, 1);
    // fH = temporal [NF, G]

    // ===== final concat + fc3 -> out =====
    concat3_kernel<<<(NF * CAT34 + 255) / 256, 256>>>((const float4*)text, (const float4*)tmpb,
                                                      (const float4*)fH, (float4*)cat, NF);
    sgemm_kernel<<<dim3(PLM / 128, NF / 128), 256>>>(cat, fc3_W, fc3_b, out, NF, PLM, CAT3, 0);
}

// round 2
// speedup vs baseline: 1.0031x; 1.0031x over previous
#include <cuda_runtime.h>

// ---------------- problem constants ----------------
#define BB    8
#define SS    2048
#define PLM   768
#define GG    256
#define NWM   50000
#define EWM   800000
#define NF    16384           // B*S
#define EF    131072
#define KSLOT 4
#define G4    (GG/4)          // 64 float4 per G-row
#define PLM4  (PLM/4)         // 192 float4 per PLM-row
#define CAT3  (PLM + 2*GG)    // 1280
#define CAT34 (CAT3/4)        // 320
#define CAT1  (GG + PLM)      // 1024
#define CAT14 (CAT1/4)        // 256

// ---------------- device scratch (no runtime alloc allowed) ----------------
__device__ __align__(16) float g_bufM[(size_t)NWM * GG];   // h+m accumulator (WM)
__device__ __align__(16) float g_bufH[(size_t)NWM * GG];   // layer output (WM)
__device__ __align__(16) float g_tmp [(size_t)NF * GG];    // per-token concept sum
__device__ __align__(16) float g_gte [(size_t)NF * GG];    // graph_text_embed
__device__ __align__(16) float g_fM  [(size_t)NF * GG];    // h+m accumulator (FSTM)
__device__ __align__(16) float g_fH  [(size_t)NF * GG];    // layer output (FSTM)
__device__ __align__(16) float g_cat [(size_t)NF * CAT3];  // concat buffer (1024 or 1280 cols)

__device__ int g_wm_rowptr[NWM + 1];
__device__ int g_wm_cur[NWM];
__device__ int g_wm_col[EWM];
__device__ int g_f_rowptr[NF + 1];
__device__ int g_f_cur[NF];
__device__ int g_f_col[EF];

// ---------------- small kernels ----------------
__global__ void zero_int_kernel(int* __restrict__ p, int n) {
    int i = blockIdx.x * blockDim.x + threadIdx.x;
    if (i < n) p[i] = 0;
}

__global__ void hist_kernel(const int* __restrict__ dst, int* __restrict__ cnt, int E) {
    int e = blockIdx.x * blockDim.x + threadIdx.x;
    if (e < E) atomicAdd(&cnt[dst[e]], 1);
}

// single block, 1024 threads. cnt_cur: in = counts, out = exclusive prefix (cursor copy)
__global__ void scan_kernel(int* __restrict__ cnt_cur, int* __restrict__ rowptr, int N, int E) {
    __shared__ int sh[1024];
    int tid = threadIdx.x;
    int chunk = (N + 1023) >> 10;
    int s0 = tid * chunk;
    int s1 = s0 + chunk; if (s1 > N) s1 = N;
    int s = 0;
    for (int i = s0; i < s1; i++) s += cnt_cur[i];
    sh[tid] = s;
    __syncthreads();
    for (int off = 1; off < 1024; off <<= 1) {
        int v = (tid >= off) ? sh[tid - off] : 0;
        __syncthreads();
        sh[tid] += v;
        __syncthreads();
    }
    int run = sh[tid] - s;  // exclusive base for this thread
    for (int i = s0; i < s1; i++) {
        int c = cnt_cur[i];
        rowptr[i]  = run;
        cnt_cur[i] = run;   // cursor for fill phase
        run += c;
    }
    if (tid == 0) rowptr[N] = E;
}

__global__ void fill_kernel(const int* __restrict__ src, const int* __restrict__ dst,
                            int* __restrict__ cur, int* __restrict__ col, int E) {
    int e = blockIdx.x * blockDim.x + threadIdx.x;
    if (e < E) {
        int d = dst[e];
        int p = atomicAdd(&cur[d], 1);
        col[p] = src[e];
    }
}

// out[n] = h[n] + sum_{edges into n} h[src]
__global__ void spmm_self_kernel(const float4* __restrict__ h,
                                 const int* __restrict__ rowptr,
                                 const int* __restrict__ col,
                                 float4* __restrict__ out, int n) {
    int node = blockIdx.x * blockDim.y + threadIdx.y;
    if (node >= n) return;
    int x = threadIdx.x;  // 0..63
    float4 acc = h[(size_t)node * G4 + x];
    int e  = rowptr[node];
    int e1 = rowptr[node + 1];
    for (; e < e1; ++e) {
        int s = __ldg(&col[e]);
        float4 v = __ldg(&h[(size_t)s * G4 + x]);
        acc.x += v.x; acc.y += v.y; acc.z += v.z; acc.w += v.w;
    }
    out[(size_t)node * G4 + x] = acc;
}

// tmp[row] = sum_{k<4} ge[t2n[row*4+k]]
__global__ void gather4sum_kernel(const float4* __restrict__ ge,
                                  const int* __restrict__ t2n,
                                  float4* __restrict__ out, int rows) {
    int row = blockIdx.x * blockDim.y + threadIdx.y;
    if (row >= rows) return;
    int x = threadIdx.x;
    float4 acc = make_float4(0.f, 0.f, 0.f, 0.f);
#pragma unroll
    for (int k = 0; k < KSLOT; k++) {
        int idx = __ldg(&t2n[row * KSLOT + k]);
        float4 v = __ldg(&ge[(size_t)idx * G4 + x]);
        acc.x += v.x; acc.y += v.y; acc.z += v.z; acc.w += v.w;
    }
    out[(size_t)row * G4 + x] = acc;
}

__global__ void gather_rows_kernel(const float4* __restrict__ src,
                                   const int* __restrict__ ids,
                                   float4* __restrict__ out, int rows) {
    int row = blockIdx.x * blockDim.y + threadIdx.y;
    if (row >= rows) return;
    int id = ids[row];
    out[(size_t)row * G4 + threadIdx.x] = src[(size_t)id * G4 + threadIdx.x];
}

// cat1[row, :] = [tmp(256) | text(768)]  -> 256 float4 per row
__global__ void concat2_kernel(const float4* __restrict__ a,      // 64 f4/row
                               const float4* __restrict__ btxt,   // 192 f4/row
                               float4* __restrict__ out, int rows) {
    int idx = blockIdx.x * blockDim.x + threadIdx.x;
    if (idx >= rows * CAT14) return;
    int row = idx >> 8;         // /256
    int c   = idx & 255;
    out[idx] = (c < G4) ? a[(size_t)row * G4 + c]
                        : btxt[(size_t)row * PLM4 + (c - G4)];
}

// final[row, :] = [text(768) | tmp(256) | temporal(256)] -> 320 float4 per row
__global__ void concat3_kernel(const float4* __restrict__ txt,
                               const float4* __restrict__ tmpv,
                               const float4* __restrict__ tempo,
                               float4* __restrict__ out, int rows) {
    int idx = blockIdx.x * blockDim.x + threadIdx.x;
    if (idx >= rows * CAT34) return;
    int row = idx / CAT34;
    int c   = idx - row * CAT34;
    float4 v;
    if (c < PLM4)            v = txt[(size_t)row * PLM4 + c];
    else if (c < PLM4 + G4)  v = tmpv[(size_t)row * G4 + (c - PLM4)];
    else                     v = tempo[(size_t)row * G4 + (c - PLM4 - G4)];
    out[idx] = v;
}

// ---------------- SGEMM: C = A(MxK) * B(KxN) + bias, optional relu ----------------
// 128x128 block tile, BK=8, 256 threads, 8x8 per thread (split 4+4 fragments).
// Requires: N % 128 == 0, K % 8 == 0 (true for all call sites). M arbitrary.
__global__ __launch_bounds__(256)
void sgemm_kernel(const float* __restrict__ A, const float* __restrict__ Bm,
                  const float* __restrict__ bias, float* __restrict__ C,
                  int M, int N, int K, int dorelu) {
    __shared__ float As[2][8][128];
    __shared__ float Bs[2][8][128];

    const int tid = threadIdx.x;
    const int bm = blockIdx.y * 128;
    const int bn = blockIdx.x * 128;
    const int tx = tid & 15;
    const int ty = tid >> 4;

    const int a_row = tid >> 1;         // 0..127
    const int a_k   = (tid & 1) * 4;    // 0 or 4
    const int b_k   = tid >> 5;         // 0..7
    const int b_n   = (tid & 31) * 4;   // 0..124

    const bool arow_ok = (bm + a_row) < M;
    const float* Aptr = A + (size_t)(bm + a_row) * K + a_k;
    const float* Bptr = Bm + (size_t)b_k * N + bn + b_n;

    float4 pa = arow_ok ? *(const float4*)Aptr : make_float4(0.f, 0.f, 0.f, 0.f);
    float4 pb = *(const float4*)Bptr;

    As[0][a_k + 0][a_row] = pa.x;
    As[0][a_k + 1][a_row] = pa.y;
    As[0][a_k + 2][a_row] = pa.z;
    As[0][a_k + 3][a_row] = pa.w;
    *(float4*)&Bs[0][b_k][b_n] = pb;
    __syncthreads();

    float acc[8][8];
#pragma unroll
    for (int i = 0; i < 8; i++)
#pragma unroll
        for (int j = 0; j < 8; j++) acc[i][j] = 0.f;

    const int nk = K >> 3;
    int cur = 0;
    for (int t = 0; t < nk; ++t) {
        if (t + 1 < nk) {
            int kk = (t + 1) << 3;
            pa = arow_ok ? *(const float4*)(Aptr + kk) : make_float4(0.f, 0.f, 0.f, 0.f);
            pb = *(const float4*)(Bptr + (size_t)kk * N);
        }
#pragma unroll
        for (int k = 0; k < 8; ++k) {
            float4 a0 = *(const float4*)&As[cur][k][ty * 4];
            float4 a1 = *(const float4*)&As[cur][k][64 + ty * 4];
            float4 b0 = *(const float4*)&Bs[cur][k][tx * 4];
            float4 b1 = *(const float4*)&Bs[cur][k][64 + tx * 4];
            float af[8] = {a0.x, a0.y, a0.z, a0.w, a1.x, a1.y, a1.z, a1.w};
            float bf[8] = {b0.x, b0.y, b0.z, b0.w, b1.x, b1.y, b1.z, b1.w};
#pragma unroll
            for (int i = 0; i < 8; i++)
#pragma unroll
                for (int j = 0; j < 8; j++) acc[i][j] += af[i] * bf[j];
        }
        if (t + 1 < nk) {
            int nxt = cur ^ 1;
            As[nxt][a_k + 0][a_row] = pa.x;
            As[nxt][a_k + 1][a_row] = pa.y;
            As[nxt][a_k + 2][a_row] = pa.z;
            As[nxt][a_k + 3][a_row] = pa.w;
            *(float4*)&Bs[nxt][b_k][b_n] = pb;
            __syncthreads();
            cur = nxt;
        }
    }

    float4 bv0 = *(const float4*)&bias[bn + tx * 4];
    float4 bv1 = *(const float4*)&bias[bn + 64 + tx * 4];

#pragma unroll
    for (int hi = 0; hi < 2; hi++) {
#pragma unroll
        for (int i = 0; i < 4; i++) {
            int row = bm + hi * 64 + ty * 4 + i;
            if (row < M) {
                int ii = hi * 4 + i;
                float4 o0 = make_float4(acc[ii][0] + bv0.x, acc[ii][1] + bv0.y,
                                        acc[ii][2] + bv0.z, acc[ii][3] + bv0.w);
                float4 o1 = make_float4(acc[ii][4] + bv1.x, acc[ii][5] + bv1.y,
                                        acc[ii][6] + bv1.z, acc[ii][7] + bv1.w);
                if (dorelu) {
                    o0.x = fmaxf(o0.x, 0.f); o0.y = fmaxf(o0.y, 0.f);
                    o0.z = fmaxf(o0.z, 0.f); o0.w = fmaxf(o0.w, 0.f);
                    o1.x = fmaxf(o1.x, 0.f); o1.y = fmaxf(o1.y, 0.f);
                    o1.z = fmaxf(o1.z, 0.f); o1.w = fmaxf(o1.w, 0.f);
                }
                *(float4*)&C[(size_t)row * N + bn + tx * 4]      = o0;
                *(float4*)&C[(size_t)row * N + bn + 64 + tx * 4] = o1;
            }
        }
    }
}

// ---------------- host launcher ----------------
extern "C" void kernel_launch(void* const* d_in, const int* in_sizes, int n_in,
                              void* d_out, int out_size) {
    (void)in_sizes; (void)n_in; (void)out_size;

    const float* text   = (const float*)d_in[0];   // [B,S,PLM] -> [NF, PLM]
    const float* wm_x   = (const float*)d_in[1];   // [NWM, G]
    const int*   wm_ei  = (const int*)  d_in[2];   // [2, EWM]
    const int*   t2n    = (const int*)  d_in[3];   // [NF, 4]
    const int*   fids   = (const int*)  d_in[4];   // [NF]
    const int*   f_ei   = (const int*)  d_in[5];   // [2, EF]
    // d_in[6] extra_emb: unreachable (indices always >= 2)
    const float* wm_W1  = (const float*)d_in[7];
    const float* wm_b1  = (const float*)d_in[8];
    const float* wm_W2  = (const float*)d_in[9];
    const float* wm_b2  = (const float*)d_in[10];
    const float* f_W1   = (const float*)d_in[11];
    const float* f_b1   = (const float*)d_in[12];
    const float* f_W2   = (const float*)d_in[13];
    const float* f_b2   = (const float*)d_in[14];
    const float* fc1_W  = (const float*)d_in[15];
    const float* fc1_b  = (const float*)d_in[16];
    const float* fc3_W  = (const float*)d_in[17];
    const float* fc3_b  = (const float*)d_in[18];
    float* out = (float*)d_out;

    float *bufM, *bufH, *tmpb, *gte, *fM, *fH, *cat;
    int *wrp, *wcur, *wcol, *frp, *fcur, *fcol;
    cudaGetSymbolAddress((void**)&bufM, g_bufM);
    cudaGetSymbolAddress((void**)&bufH, g_bufH);
    cudaGetSymbolAddress((void**)&tmpb, g_tmp);
    cudaGetSymbolAddress((void**)&gte,  g_gte);
    cudaGetSymbolAddress((void**)&fM,   g_fM);
    cudaGetSymbolAddress((void**)&fH,   g_fH);
    cudaGetSymbolAddress((void**)&cat,  g_cat);
    cudaGetSymbolAddress((void**)&wrp,  g_wm_rowptr);
    cudaGetSymbolAddress((void**)&wcur, g_wm_cur);
    cudaGetSymbolAddress((void**)&wcol, g_wm_col);
    cudaGetSymbolAddress((void**)&frp,  g_f_rowptr);
    cudaGetSymbolAddress((void**)&fcur, g_f_cur);
    cudaGetSymbolAddress((void**)&fcol, g_f_col);

    const dim3 bSp(64, 4);

    // ===== WM CSR build (rows = dst, cols = src) =====
    zero_int_kernel<<<(NWM + 255) / 256, 256>>>(wcur, NWM);
    hist_kernel<<<(EWM + 255) / 256, 256>>>(wm_ei + EWM, wcur, EWM);
    scan_kernel<<<1, 1024>>>(wcur, wrp, NWM, EWM);
    fill_kernel<<<(EWM + 255) / 256, 256>>>(wm_ei, wm_ei + EWM, wcur, wcol, EWM);

    // ===== WM GNN: 2 layers =====
    spmm_self_kernel<<<(NWM + 3) / 4, bSp>>>((const float4*)wm_x, wrp, wcol, (float4*)bufM, NWM);
    sgemm_kernel<<<dim3(GG / 128, (NWM + 127) / 128), 256>>>(bufM, wm_W1, wm_b1, bufH, NWM, GG, GG, 1);
    spmm_self_kernel<<<(NWM + 3) / 4, bSp>>>((const float4*)bufH, wrp, wcol, (float4*)bufM, NWM);
    sgemm_kernel<<<dim3(GG / 128, (NWM + 127) / 128), 256>>>(bufM, wm_W2, wm_b2, bufH, NWM, GG, GG, 1);
    // bufH = graph_embeddings [NWM, G]

    // ===== token concept sum + fc1 =====
    gather4sum_kernel<<<(NF + 3) / 4, bSp>>>((const float4*)bufH, t2n, (float4*)tmpb, NF);
    concat2_kernel<<<(NF * CAT14 + 255) / 256, 256>>>((const float4*)tmpb, (const float4*)text,
                                                      (float4*)cat, NF);
    sgemm_kernel<<<dim3(GG / 128, NF / 128), 256>>>(cat, fc1_W, fc1_b, gte, NF, GG, CAT1, 0);

    // ===== FSTM: gather + CSR + 2 layers =====
    gather_rows_kernel<<<(NF + 3) / 4, bSp>>>((const float4*)gte, fids, (float4*)fH, NF);

    zero_int_kernel<<<(NF + 255) / 256, 256>>>(fcur, NF);
    hist_kernel<<<(EF + 255) / 256, 256>>>(f_ei + EF, fcur, EF);
    scan_kernel<<<1, 1024>>>(fcur, frp, NF, EF);
    fill_kernel<<<(EF + 255) / 256, 256>>>(f_ei, f_ei + EF, fcur, fcol, EF);

    spmm_self_kernel<<<(NF + 3) / 4, bSp>>>((const float4*)fH, frp, fcol, (float4*)fM, NF);
    sgemm_kernel<<<dim3(GG / 128, NF / 128), 256>>>(fM, f_W1, f_b1, fH, NF, GG, GG, 1);
    spmm_self_kernel<<<(NF + 3) / 4, bSp>>>((const float4*)fH, frp, fcol, (float4*)fM, NF);
    sgemm_kernel<<<dim3(GG / 128, NF / 128), 256>>>(fM, f_W2, f_b2, fH, NF, GG, GG, 1);
    // fH = temporal [NF, G]

    // ===== final concat + fc3 -> out =====
    concat3_kernel<<<(NF * CAT34 + 255) / 256, 256>>>((const float4*)text, (const float4*)tmpb,
                                                      (const float4*)fH, (float4*)cat, NF);
    sgemm_kernel<<<dim3(PLM / 128, NF / 128), 256>>>(cat, fc3_W, fc3_b, out, NF, PLM, CAT3, 0);
}

// round 3
// speedup vs baseline: 1.6054x; 1.6005x over previous
#include <cuda_runtime.h>
#include <cuda_bf16.h>
#include <cstdint>

// ---------------- problem constants ----------------
#define BB    8
#define SS    2048
#define PLM   768
#define GG    256
#define NWM   50000
#define EWM   800000
#define NF    16384           // B*S
#define EF    131072
#define KSLOT 4
#define G4    (GG/4)          // 64 float4 per G-row
#define PLM4  (PLM/4)         // 192 float4 per PLM-row
#define CAT3  (PLM + 2*GG)    // 1280
#define CAT34 (CAT3/4)        // 320
#define CAT1  (GG + PLM)      // 1024
#define CAT14 (CAT1/4)        // 256

// ---------------- device scratch (no runtime alloc allowed) ----------------
__device__ __align__(16) float g_bufM[(size_t)NWM * GG];   // h+m accumulator (WM)
__device__ __align__(16) float g_bufH[(size_t)NWM * GG];   // layer output (WM)
__device__ __align__(16) float g_tmp [(size_t)NF * GG];    // per-token concept sum
__device__ __align__(16) float g_gte [(size_t)NF * GG];    // graph_text_embed
__device__ __align__(16) float g_fM  [(size_t)NF * GG];    // h+m accumulator (FSTM)
__device__ __align__(16) float g_fH  [(size_t)NF * GG];    // layer output (FSTM)
__device__ __align__(16) float g_cat [(size_t)NF * CAT3];  // concat buffer

__device__ int g_wm_rowptr[NWM + 1];
__device__ int g_wm_cur[NWM];
__device__ int g_wm_col[EWM];
__device__ int g_f_rowptr[NF + 1];
__device__ int g_f_cur[NF];
__device__ int g_f_col[EF];

// ---------------- small kernels ----------------
__global__ void zero_int_kernel(int* __restrict__ p, int n) {
    int i = blockIdx.x * blockDim.x + threadIdx.x;
    if (i < n) p[i] = 0;
}

__global__ void hist_kernel(const int* __restrict__ dst, int* __restrict__ cnt, int E) {
    int e = blockIdx.x * blockDim.x + threadIdx.x;
    if (e < E) atomicAdd(&cnt[dst[e]], 1);
}

// single block, 1024 threads. cnt_cur: in = counts, out = exclusive prefix (cursor copy)
__global__ void scan_kernel(int* __restrict__ cnt_cur, int* __restrict__ rowptr, int N, int E) {
    __shared__ int sh[1024];
    int tid = threadIdx.x;
    int chunk = (N + 1023) >> 10;
    int s0 = tid * chunk;
    int s1 = s0 + chunk; if (s1 > N) s1 = N;
    int s = 0;
    for (int i = s0; i < s1; i++) s += cnt_cur[i];
    sh[tid] = s;
    __syncthreads();
    for (int off = 1; off < 1024; off <<= 1) {
        int v = (tid >= off) ? sh[tid - off] : 0;
        __syncthreads();
        sh[tid] += v;
        __syncthreads();
    }
    int run = sh[tid] - s;  // exclusive base for this thread
    for (int i = s0; i < s1; i++) {
        int c = cnt_cur[i];
        rowptr[i]  = run;
        cnt_cur[i] = run;   // cursor for fill phase
        run += c;
    }
    if (tid == 0) rowptr[N] = E;
}

__global__ void fill_kernel(const int* __restrict__ src, const int* __restrict__ dst,
                            int* __restrict__ cur, int* __restrict__ col, int E) {
    int e = blockIdx.x * blockDim.x + threadIdx.x;
    if (e < E) {
        int d = dst[e];
        int p = atomicAdd(&cur[d], 1);
        col[p] = src[e];
    }
}

// out[n] = h[n] + sum_{edges into n} h[src]
__global__ void spmm_self_kernel(const float4* __restrict__ h,
                                 const int* __restrict__ rowptr,
                                 const int* __restrict__ col,
                                 float4* __restrict__ out, int n) {
    int node = blockIdx.x * blockDim.y + threadIdx.y;
    if (node >= n) return;
    int x = threadIdx.x;  // 0..63
    float4 acc = h[(size_t)node * G4 + x];
    int e  = rowptr[node];
    int e1 = rowptr[node + 1];
    for (; e < e1; ++e) {
        int s = __ldg(&col[e]);
        float4 v = __ldg(&h[(size_t)s * G4 + x]);
        acc.x += v.x; acc.y += v.y; acc.z += v.z; acc.w += v.w;
    }
    out[(size_t)node * G4 + x] = acc;
}

// tmp[row] = sum_{k<4} ge[t2n[row*4+k]]
__global__ void gather4sum_kernel(const float4* __restrict__ ge,
                                  const int* __restrict__ t2n,
                                  float4* __restrict__ out, int rows) {
    int row = blockIdx.x * blockDim.y + threadIdx.y;
    if (row >= rows) return;
    int x = threadIdx.x;
    float4 acc = make_float4(0.f, 0.f, 0.f, 0.f);
#pragma unroll
    for (int k = 0; k < KSLOT; k++) {
        int idx = __ldg(&t2n[row * KSLOT + k]);
        float4 v = __ldg(&ge[(size_t)idx * G4 + x]);
        acc.x += v.x; acc.y += v.y; acc.z += v.z; acc.w += v.w;
    }
    out[(size_t)row * G4 + x] = acc;
}

__global__ void gather_rows_kernel(const float4* __restrict__ src,
                                   const int* __restrict__ ids,
                                   float4* __restrict__ out, int rows) {
    int row = blockIdx.x * blockDim.y + threadIdx.y;
    if (row >= rows) return;
    int id = ids[row];
    out[(size_t)row * G4 + threadIdx.x] = src[(size_t)id * G4 + threadIdx.x];
}

// cat1[row, :] = [tmp(256) | text(768)]  -> 256 float4 per row
__global__ void concat2_kernel(const float4* __restrict__ a,
                               const float4* __restrict__ btxt,
                               float4* __restrict__ out, int rows) {
    int idx = blockIdx.x * blockDim.x + threadIdx.x;
    if (idx >= rows * CAT14) return;
    int row = idx >> 8;         // /256
    int c   = idx & 255;
    out[idx] = (c < G4) ? a[(size_t)row * G4 + c]
                        : btxt[(size_t)row * PLM4 + (c - G4)];
}

// final[row, :] = [text(768) | tmp(256) | temporal(256)] -> 320 float4 per row
__global__ void concat3_kernel(const float4* __restrict__ txt,
                               const float4* __restrict__ tmpv,
                               const float4* __restrict__ tempo,
                               float4* __restrict__ out, int rows) {
    int idx = blockIdx.x * blockDim.x + threadIdx.x;
    if (idx >= rows * CAT34) return;
    int row = idx / CAT34;
    int c   = idx - row * CAT34;
    float4 v;
    if (c < PLM4)            v = txt[(size_t)row * PLM4 + c];
    else if (c < PLM4 + G4)  v = tmpv[(size_t)row * G4 + (c - PLM4)];
    else                     v = tempo[(size_t)row * G4 + (c - PLM4 - G4)];
    out[idx] = v;
}

// ---------------- split-bf16 tensor-core GEMM ----------------
// C = A(MxK) * B(KxN) + bias, optional relu.
// fp32 emulated by hi/lo bf16 split: acc += Ah*Bh + Ah*Bl + Al*Bh  (error ~2^-18)
// 128x128x16 block tile, 256 threads (8 warps, 4x2), warp tile 32x64,
// mma.sync.aligned.m16n8k16 bf16, fp32 accumulate.
// Requires N % 128 == 0, K % 16 == 0 (true for all call sites). M arbitrary.

__device__ __forceinline__ void split_pair(float x0, float x1, uint32_t& hi, uint32_t& lo) {
    __nv_bfloat16 h0 = __float2bfloat16_rn(x0);
    __nv_bfloat16 h1 = __float2bfloat16_rn(x1);
    float r0 = x0 - __bfloat162float(h0);
    float r1 = x1 - __bfloat162float(h1);
    __nv_bfloat16 l0 = __float2bfloat16_rn(r0);
    __nv_bfloat16 l1 = __float2bfloat16_rn(r1);
    hi = ((uint32_t)__bfloat16_as_ushort(h1) << 16) | (uint32_t)__bfloat16_as_ushort(h0);
    lo = ((uint32_t)__bfloat16_as_ushort(l1) << 16) | (uint32_t)__bfloat16_as_ushort(l0);
}

__device__ __forceinline__ void mma16816(float* c, const uint32_t* a, uint32_t b0, uint32_t b1) {
    asm volatile(
        "mma.sync.aligned.m16n8k16.row.col.f32.bf16.bf16.f32 "
        "{%0,%1,%2,%3}, {%4,%5,%6,%7}, {%8,%9}, {%0,%1,%2,%3};\n"
        : "+f"(c[0]), "+f"(c[1]), "+f"(c[2]), "+f"(c[3])
        : "r"(a[0]), "r"(a[1]), "r"(a[2]), "r"(a[3]), "r"(b0), "r"(b1));
}

#define SMP 136   // padded row length (u32) -> conflict-free fragment LDS

__global__ __launch_bounds__(256, 2)
void mgemm_kernel(const float* __restrict__ A, const float* __restrict__ Bm,
                  const float* __restrict__ bias, float* __restrict__ C,
                  int M, int N, int K, int dorelu) {
    // [buf][split(hi=0,lo=1)][k2 (k-pair 0..7)][m or n, padded]
    __shared__ __align__(16) uint32_t As[2][2][8][SMP];
    __shared__ __align__(16) uint32_t Bs[2][2][8][SMP];

    const int tid  = threadIdx.x;
    const int lane = tid & 31;
    const int wid  = tid >> 5;
    const int wm   = wid & 3;        // warp row  (4)
    const int wn   = wid >> 2;       // warp col  (2)
    const int g    = lane >> 2;      // groupID 0..7
    const int tg   = lane & 3;       // thread-in-group 0..3

    const int bm = blockIdx.y * 128;
    const int bn = blockIdx.x * 128;

    // --- A staging indices: thread covers row am, k = ak..ak+7 ---
    const int am = tid >> 1;           // 0..127
    const int ak = (tid & 1) * 8;      // 0 or 8
    const bool aok = (bm + am) < M;
    const float* Ap = A + (size_t)(bm + am) * K + ak;

    // --- B staging indices: thread covers k-pair bk2, n = bn4..bn4+3 ---
    const int bk2 = tid >> 5;          // 0..7
    const int bn4 = (tid & 31) * 4;    // 0..124
    const float* Bp = Bm + (size_t)(2 * bk2) * N + bn + bn4;

    float4 pa0, pa1, pbe, pbo;
    const float4 fz = make_float4(0.f, 0.f, 0.f, 0.f);

    pa0 = aok ? *(const float4*)(Ap)     : fz;
    pa1 = aok ? *(const float4*)(Ap + 4) : fz;
    pbe = *(const float4*)(Bp);
    pbo = *(const float4*)(Bp + N);

    // stage helpers
    auto stageA = [&](int buf, float4 v0, float4 v1) {
        uint32_t h, l;
        int k2 = ak >> 1;   // 0 or 4
        split_pair(v0.x, v0.y, h, l); As[buf][0][k2+0][am] = h; As[buf][1][k2+0][am] = l;
        split_pair(v0.z, v0.w, h, l); As[buf][0][k2+1][am] = h; As[buf][1][k2+1][am] = l;
        split_pair(v1.x, v1.y, h, l); As[buf][0][k2+2][am] = h; As[buf][1][k2+2][am] = l;
        split_pair(v1.z, v1.w, h, l); As[buf][0][k2+3][am] = h; As[buf][1][k2+3][am] = l;
    };
    auto stageB = [&](int buf, float4 e, float4 o) {
        uint4 hv, lv;
        split_pair(e.x, o.x, hv.x, lv.x);
        split_pair(e.y, o.y, hv.y, lv.y);
        split_pair(e.z, o.z, hv.z, lv.z);
        split_pair(e.w, o.w, hv.w, lv.w);
        *(uint4*)&Bs[buf][0][bk2][bn4] = hv;
        *(uint4*)&Bs[buf][1][bk2][bn4] = lv;
    };

    stageA(0, pa0, pa1);
    stageB(0, pbe, pbo);
    __syncthreads();

    float acc[2][8][4];
#pragma unroll
    for (int i = 0; i < 2; i++)
#pragma unroll
        for (int j = 0; j < 8; j++)
#pragma unroll
            for (int q = 0; q < 4; q++) acc[i][j][q] = 0.f;

    const int nk = K >> 4;
    int cur = 0;
    for (int t = 0; t < nk; ++t) {
        if (t + 1 < nk) {
            int kk = (t + 1) << 4;
            pa0 = aok ? *(const float4*)(Ap + kk)     : fz;
            pa1 = aok ? *(const float4*)(Ap + kk + 4) : fz;
            pbe = *(const float4*)(Bp + (size_t)kk * N);
            pbo = *(const float4*)(Bp + (size_t)(kk + 1) * N);
        }

        // ---- compute on buffer `cur` ----
        uint32_t af[2][2][4];   // [mtile][split][reg]
#pragma unroll
        for (int mt = 0; mt < 2; mt++) {
            int m = wm * 32 + mt * 16 + g;
#pragma unroll
            for (int s = 0; s < 2; s++) {
                af[mt][s][0] = As[cur][s][tg    ][m];
                af[mt][s][1] = As[cur][s][tg    ][m + 8];
                af[mt][s][2] = As[cur][s][tg + 4][m];
                af[mt][s][3] = As[cur][s][tg + 4][m + 8];
            }
        }
#pragma unroll
        for (int nt = 0; nt < 8; nt++) {
            int n = wn * 64 + nt * 8 + g;
            uint32_t bh0 = Bs[cur][0][tg    ][n];
            uint32_t bh1 = Bs[cur][0][tg + 4][n];
            uint32_t bl0 = Bs[cur][1][tg    ][n];
            uint32_t bl1 = Bs[cur][1][tg + 4][n];
#pragma unroll
            for (int mt = 0; mt < 2; mt++) {
                mma16816(acc[mt][nt], af[mt][0], bh0, bh1);  // hi*hi
                mma16816(acc[mt][nt], af[mt][0], bl0, bl1);  // hi*lo
                mma16816(acc[mt][nt], af[mt][1], bh0, bh1);  // lo*hi
            }
        }

        if (t + 1 < nk) {
            int nxt = cur ^ 1;
            stageA(nxt, pa0, pa1);
            stageB(nxt, pbe, pbo);
            __syncthreads();
            cur = nxt;
        }
    }

    // ---- epilogue: bias + optional relu ----
#pragma unroll
    for (int nt = 0; nt < 8; nt++) {
        int col = bn + wn * 64 + nt * 8 + 2 * tg;
        float2 bv = *(const float2*)&bias[col];
#pragma unroll
        for (int mt = 0; mt < 2; mt++) {
            int row0 = bm + wm * 32 + mt * 16 + g;
            float v0 = acc[mt][nt][0] + bv.x;
            float v1 = acc[mt][nt][1] + bv.y;
            float v2 = acc[mt][nt][2] + bv.x;
            float v3 = acc[mt][nt][3] + bv.y;
            if (dorelu) {
                v0 = fmaxf(v0, 0.f); v1 = fmaxf(v1, 0.f);
                v2 = fmaxf(v2, 0.f); v3 = fmaxf(v3, 0.f);
            }
            if (row0 < M) {
                float2 o = make_float2(v0, v1);
                *(float2*)&C[(size_t)row0 * N + col] = o;
            }
            if (row0 + 8 < M) {
                float2 o = make_float2(v2, v3);
                *(float2*)&C[(size_t)(row0 + 8) * N + col] = o;
            }
        }
    }
}

// ---------------- host launcher ----------------
extern "C" void kernel_launch(void* const* d_in, const int* in_sizes, int n_in,
                              void* d_out, int out_size) {
    (void)in_sizes; (void)n_in; (void)out_size;

    const float* text   = (const float*)d_in[0];   // [B,S,PLM] -> [NF, PLM]
    const float* wm_x   = (const float*)d_in[1];   // [NWM, G]
    const int*   wm_ei  = (const int*)  d_in[2];   // [2, EWM]
    const int*   t2n    = (const int*)  d_in[3];   // [NF, 4]
    const int*   fids   = (const int*)  d_in[4];   // [NF]
    const int*   f_ei   = (const int*)  d_in[5];   // [2, EF]
    // d_in[6] extra_emb: unreachable (indices always >= 2)
    const float* wm_W1  = (const float*)d_in[7];
    const float* wm_b1  = (const float*)d_in[8];
    const float* wm_W2  = (const float*)d_in[9];
    const float* wm_b2  = (const float*)d_in[10];
    const float* f_W1   = (const float*)d_in[11];
    const float* f_b1   = (const float*)d_in[12];
    const float* f_W2   = (const float*)d_in[13];
    const float* f_b2   = (const float*)d_in[14];
    const float* fc1_W  = (const float*)d_in[15];
    const float* fc1_b  = (const float*)d_in[16];
    const float* fc3_W  = (const float*)d_in[17];
    const float* fc3_b  = (const float*)d_in[18];
    float* out = (float*)d_out;

    float *bufM, *bufH, *tmpb, *gte, *fM, *fH, *cat;
    int *wrp, *wcur, *wcol, *frp, *fcur, *fcol;
    cudaGetSymbolAddress((void**)&bufM, g_bufM);
    cudaGetSymbolAddress((void**)&bufH, g_bufH);
    cudaGetSymbolAddress((void**)&tmpb, g_tmp);
    cudaGetSymbolAddress((void**)&gte,  g_gte);
    cudaGetSymbolAddress((void**)&fM,   g_fM);
    cudaGetSymbolAddress((void**)&fH,   g_fH);
    cudaGetSymbolAddress((void**)&cat,  g_cat);
    cudaGetSymbolAddress((void**)&wrp,  g_wm_rowptr);
    cudaGetSymbolAddress((void**)&wcur, g_wm_cur);
    cudaGetSymbolAddress((void**)&wcol, g_wm_col);
    cudaGetSymbolAddress((void**)&frp,  g_f_rowptr);
    cudaGetSymbolAddress((void**)&fcur, g_f_cur);
    cudaGetSymbolAddress((void**)&fcol, g_f_col);

    const dim3 bSp(64, 4);

    // ===== WM CSR build (rows = dst, cols = src) =====
    zero_int_kernel<<<(NWM + 255) / 256, 256>>>(wcur, NWM);
    hist_kernel<<<(EWM + 255) / 256, 256>>>(wm_ei + EWM, wcur, EWM);
    scan_kernel<<<1, 1024>>>(wcur, wrp, NWM, EWM);
    fill_kernel<<<(EWM + 255) / 256, 256>>>(wm_ei, wm_ei + EWM, wcur, wcol, EWM);

    // ===== WM GNN: 2 layers =====
    spmm_self_kernel<<<(NWM + 3) / 4, bSp>>>((const float4*)wm_x, wrp, wcol, (float4*)bufM, NWM);
    mgemm_kernel<<<dim3(GG / 128, (NWM + 127) / 128), 256>>>(bufM, wm_W1, wm_b1, bufH, NWM, GG, GG, 1);
    spmm_self_kernel<<<(NWM + 3) / 4, bSp>>>((const float4*)bufH, wrp, wcol, (float4*)bufM, NWM);
    mgemm_kernel<<<dim3(GG / 128, (NWM + 127) / 128), 256>>>(bufM, wm_W2, wm_b2, bufH, NWM, GG, GG, 1);
    // bufH = graph_embeddings [NWM, G]

    // ===== token concept sum + fc1 =====
    gather4sum_kernel<<<(NF + 3) / 4, bSp>>>((const float4*)bufH, t2n, (float4*)tmpb, NF);
    concat2_kernel<<<(NF * CAT14 + 255) / 256, 256>>>((const float4*)tmpb, (const float4*)text,
                                                      (float4*)cat, NF);
    mgemm_kernel<<<dim3(GG / 128, NF / 128), 256>>>(cat, fc1_W, fc1_b, gte, NF, GG, CAT1, 0);

    // ===== FSTM: gather + CSR + 2 layers =====
    gather_rows_kernel<<<(NF + 3) / 4, bSp>>>((const float4*)gte, fids, (float4*)fH, NF);

    zero_int_kernel<<<(NF + 255) / 256, 256>>>(fcur, NF);
    hist_kernel<<<(EF + 255) / 256, 256>>>(f_ei + EF, fcur, EF);
    scan_kernel<<<1, 1024>>>(fcur, frp, NF, EF);
    fill_kernel<<<(EF + 255) / 256, 256>>>(f_ei, f_ei + EF, fcur, fcol, EF);

    spmm_self_kernel<<<(NF + 3) / 4, bSp>>>((const float4*)fH, frp, fcol, (float4*)fM, NF);
    mgemm_kernel<<<dim3(GG / 128, NF / 128), 256>>>(fM, f_W1, f_b1, fH, NF, GG, GG, 1);
    spmm_self_kernel<<<(NF + 3) / 4, bSp>>>((const float4*)fH, frp, fcol, (float4*)fM, NF);
    mgemm_kernel<<<dim3(GG / 128, NF / 128), 256>>>(fM, f_W2, f_b2, fH, NF, GG, GG, 1);
    // fH = temporal [NF, G]

    // ===== final concat + fc3 -> out =====
    concat3_kernel<<<(NF * CAT34 + 255) / 256, 256>>>((const float4*)text, (const float4*)tmpb,
                                                      (const float4*)fH, (float4*)cat, NF);
    mgemm_kernel<<<dim3(PLM / 128, NF / 128), 256>>>(cat, fc3_W, fc3_b, out, NF, PLM, CAT3, 0);
}